// round 1
// baseline (speedup 1.0000x reference)
#include <cuda_runtime.h>
#include <math.h>

#define N_NODES 10000
#define E_EDGES 320000
#define E_TOT   330000   // + self loops
#define HID     256
#define DOUT    32

// ---------------- scratch (device globals; no allocation allowed) ----------------
__device__ float g_hidden[N_NODES * HID];
__device__ float g_xl0[N_NODES * HID];
__device__ float g_xr0[N_NODES * HID];
__device__ float g_out0[N_NODES * HID];
__device__ float g_h1[N_NODES * HID];
__device__ float g_xl1[N_NODES * DOUT];
__device__ float g_xr1[N_NODES * DOUT];
__device__ float g_out1[N_NODES * DOUT];
__device__ float g_logit0[E_TOT * 2];
__device__ float g_ex0[E_TOT * 2];
__device__ float g_logit1[E_TOT * 2];
__device__ float g_ex1[E_TOT * 2];
__device__ float g_max0[N_NODES * 2];
__device__ float g_sum0[N_NODES * 2];
__device__ float g_max1[N_NODES * 2];
__device__ float g_sum1[N_NODES * 2];
__device__ float g_ea_mean;

// ---------------- helpers ----------------
__device__ __forceinline__ float lrelu(float v) { return v > 0.f ? v : 0.2f * v; }

// atomic float max via signed-max / unsigned-min bit trick (init = -inf bits)
__device__ __forceinline__ void atomicMaxF(float* addr, float val) {
    if (val >= 0.f)
        atomicMax((int*)addr, __float_as_int(val));
    else
        atomicMin((unsigned int*)addr, (unsigned int)__float_as_int(val));
}

__device__ __forceinline__ float warp_sum(float v) {
    #pragma unroll
    for (int o = 16; o > 0; o >>= 1) v += __shfl_xor_sync(0xffffffffu, v, o);
    return v;
}

// ---------------- init: zero accumulators, -inf maxes ----------------
__global__ void k_init() {
    int i = blockIdx.x * blockDim.x + threadIdx.x;
    int stride = gridDim.x * blockDim.x;
    const float ninf = __int_as_float(0xFF800000);
    for (int j = i; j < N_NODES * HID; j += stride) g_out0[j] = 0.f;
    for (int j = i; j < N_NODES * DOUT; j += stride) g_out1[j] = 0.f;
    for (int j = i; j < N_NODES * 2; j += stride) {
        g_sum0[j] = 0.f; g_sum1[j] = 0.f;
        g_max0[j] = ninf; g_max1[j] = ninf;
    }
}

// ---------------- edge_attr mean (ED=1) ----------------
__global__ void k_eamean(const float* __restrict__ ea) {
    __shared__ float sh[1024];
    float s = 0.f;
    for (int i = threadIdx.x; i < E_EDGES; i += 1024) s += ea[i];
    sh[threadIdx.x] = s;
    __syncthreads();
    for (int o = 512; o > 0; o >>= 1) {
        if (threadIdx.x < o) sh[threadIdx.x] += sh[threadIdx.x + o];
        __syncthreads();
    }
    if (threadIdx.x == 0) g_ea_mean = sh[0] / (float)E_EDGES;
}

// ---------------- tiled SGEMM with bias: C[M,Nc] = A[M,K] @ B[K,Nc] + bias ----------------
template<int BM, int BN, int BK, int TM, int TN>
__global__ void sgemm_bias(const float* __restrict__ A, const float* __restrict__ B,
                           const float* __restrict__ bias, float* __restrict__ C,
                           int M, int Nc, int K) {
    __shared__ float As[BK][BM];
    __shared__ float Bs[BK][BN];
    constexpr int TX = BN / TN;          // threads along N
    constexpr int NTHREADS = TX * (BM / TM);
    const int tid = threadIdx.x;
    const int tx = tid % TX, ty = tid / TX;
    const int row0 = blockIdx.y * BM, col0 = blockIdx.x * BN;

    float acc[TM][TN];
    #pragma unroll
    for (int m = 0; m < TM; m++)
        #pragma unroll
        for (int n = 0; n < TN; n++) acc[m][n] = 0.f;

    for (int k0 = 0; k0 < K; k0 += BK) {
        #pragma unroll
        for (int i = tid; i < BM * BK; i += NTHREADS) {
            int r = i / BK, c = i % BK;
            int gr = row0 + r;
            As[c][r] = (gr < M) ? A[(long)gr * K + k0 + c] : 0.f;
        }
        #pragma unroll
        for (int i = tid; i < BK * BN; i += NTHREADS) {
            int r = i / BN, c = i % BN;
            Bs[r][c] = B[(long)(k0 + r) * Nc + col0 + c];
        }
        __syncthreads();
        #pragma unroll
        for (int kk = 0; kk < BK; kk++) {
            float a[TM], b[TN];
            #pragma unroll
            for (int m = 0; m < TM; m++) a[m] = As[kk][ty * TM + m];
            #pragma unroll
            for (int n = 0; n < TN; n++) b[n] = Bs[kk][tx * TN + n];
            #pragma unroll
            for (int m = 0; m < TM; m++)
                #pragma unroll
                for (int n = 0; n < TN; n++) acc[m][n] += a[m] * b[n];
        }
        __syncthreads();
    }
    #pragma unroll
    for (int m = 0; m < TM; m++) {
        int gr = row0 + ty * TM + m;
        if (gr >= M) continue;
        #pragma unroll
        for (int n = 0; n < TN; n++) {
            int gc = col0 + tx * TN + n;
            C[(long)gr * Nc + gc] = acc[m][n] + bias[gc];
        }
    }
}

// ---------------- layer-0 edge logits: warp per edge ----------------
__global__ void k_logits0(const int* __restrict__ ei, const float* __restrict__ eattr,
                          const float* __restrict__ att, const float* __restrict__ We) {
    int e = blockIdx.x * (blockDim.x >> 5) + (threadIdx.x >> 5);
    if (e >= E_TOT) return;
    int lane = threadIdx.x & 31;
    int src, dst; float ea;
    if (e < E_EDGES) { src = ei[e]; dst = ei[E_EDGES + e]; ea = eattr[e]; }
    else { src = dst = e - E_EDGES; ea = g_ea_mean; }

    const float4* xl4 = (const float4*)g_xl0;
    const float4* xr4 = (const float4*)g_xr0;
    const float4* We4 = (const float4*)We;
    const float4* at4 = (const float4*)att;

    float p0, p1;
    {
        int i = lane;  // head 0 (indices 0..127)
        float4 a = xl4[src * 64 + i], b = xr4[dst * 64 + i];
        float4 w = We4[i], t = at4[i];
        p0 = lrelu(a.x + b.x + ea * w.x) * t.x
           + lrelu(a.y + b.y + ea * w.y) * t.y
           + lrelu(a.z + b.z + ea * w.z) * t.z
           + lrelu(a.w + b.w + ea * w.w) * t.w;
        i = lane + 32; // head 1 (indices 128..255)
        a = xl4[src * 64 + i]; b = xr4[dst * 64 + i];
        w = We4[i]; t = at4[i];
        p1 = lrelu(a.x + b.x + ea * w.x) * t.x
           + lrelu(a.y + b.y + ea * w.y) * t.y
           + lrelu(a.z + b.z + ea * w.z) * t.z
           + lrelu(a.w + b.w + ea * w.w) * t.w;
    }
    p0 = warp_sum(p0);
    p1 = warp_sum(p1);
    if (lane == 0) {
        g_logit0[e * 2 + 0] = p0;
        g_logit0[e * 2 + 1] = p1;
        atomicMaxF(&g_max0[dst * 2 + 0], p0);
        atomicMaxF(&g_max0[dst * 2 + 1], p1);
    }
}

// ---------------- exp + segment sum (generic): thread per (edge, head) ----------------
__global__ void k_expsum(const int* __restrict__ ei, const float* __restrict__ logit,
                         const float* __restrict__ maxb, float* __restrict__ ex,
                         float* __restrict__ sumb) {
    int idx = blockIdx.x * blockDim.x + threadIdx.x;
    if (idx >= E_TOT * 2) return;
    int e = idx >> 1, h = idx & 1;
    int dst = (e < E_EDGES) ? ei[E_EDGES + e] : (e - E_EDGES);
    float v = expf(logit[idx] - maxb[dst * 2 + h]);
    ex[idx] = v;
    atomicAdd(&sumb[dst * 2 + h], v);
}

// ---------------- layer-0 aggregation: warp per edge, atomicAdd ----------------
__global__ void k_agg0(const int* __restrict__ ei) {
    int e = blockIdx.x * (blockDim.x >> 5) + (threadIdx.x >> 5);
    if (e >= E_TOT) return;
    int lane = threadIdx.x & 31;
    int src, dst;
    if (e < E_EDGES) { src = ei[e]; dst = ei[E_EDGES + e]; }
    else { src = dst = e - E_EDGES; }

    float a0 = g_ex0[e * 2 + 0] / (g_sum0[dst * 2 + 0] + 1e-16f);
    float a1 = g_ex0[e * 2 + 1] / (g_sum0[dst * 2 + 1] + 1e-16f);
    const float4* xl4 = (const float4*)g_xl0;
    #pragma unroll
    for (int s = 0; s < 2; s++) {
        int i = lane + s * 32;
        float al = (i < 32) ? a0 : a1;
        float4 v = xl4[src * 64 + i];
        float* o = &g_out0[dst * HID + i * 4];
        atomicAdd(o + 0, al * v.x);
        atomicAdd(o + 1, al * v.y);
        atomicAdd(o + 2, al * v.z);
        atomicAdd(o + 3, al * v.w);
    }
}

// ---------------- residual + bias + LayerNorm + ReLU (HID=256): warp per node ----------------
__global__ void k_resid_ln0(const float* __restrict__ bias0, const float* __restrict__ g0,
                            const float* __restrict__ be0) {
    int r = blockIdx.x * (blockDim.x >> 5) + (threadIdx.x >> 5);
    if (r >= N_NODES) return;
    int lane = threadIdx.x & 31;
    const float4* o4 = (const float4*)g_out0;
    const float4* h4 = (const float4*)g_hidden;
    const float4* b4 = (const float4*)bias0;
    const float4* gg4 = (const float4*)g0;
    const float4* bb4 = (const float4*)be0;

    float4 t[2];
    float s = 0.f, sq = 0.f;
    #pragma unroll
    for (int k = 0; k < 2; k++) {
        int i = lane + k * 32;
        float4 a = o4[r * 64 + i], b = b4[i], h = h4[r * 64 + i];
        float4 v;
        v.x = a.x + b.x + h.x; v.y = a.y + b.y + h.y;
        v.z = a.z + b.z + h.z; v.w = a.w + b.w + h.w;
        t[k] = v;
        s  += v.x + v.y + v.z + v.w;
        sq += v.x * v.x + v.y * v.y + v.z * v.z + v.w * v.w;
    }
    s = warp_sum(s);
    sq = warp_sum(sq);
    float mu = s / 256.f;
    float var = sq / 256.f - mu * mu;
    float rs = rsqrtf(var + 1e-5f);
    float4* out4 = (float4*)g_h1;
    #pragma unroll
    for (int k = 0; k < 2; k++) {
        int i = lane + k * 32;
        float4 g = gg4[i], bb = bb4[i], v = t[k];
        float4 o;
        o.x = fmaxf(0.f, (v.x - mu) * rs * g.x + bb.x);
        o.y = fmaxf(0.f, (v.y - mu) * rs * g.y + bb.y);
        o.z = fmaxf(0.f, (v.z - mu) * rs * g.z + bb.z);
        o.w = fmaxf(0.f, (v.w - mu) * rs * g.w + bb.w);
        out4[r * 64 + i] = o;
    }
}

// ---------------- layer-1 edge logits: warp per edge (8 active lanes) ----------------
__global__ void k_logits1(const int* __restrict__ ei, const float* __restrict__ eattr,
                          const float* __restrict__ att, const float* __restrict__ We) {
    int e = blockIdx.x * (blockDim.x >> 5) + (threadIdx.x >> 5);
    if (e >= E_TOT) return;
    int lane = threadIdx.x & 31;
    int src, dst; float ea;
    if (e < E_EDGES) { src = ei[e]; dst = ei[E_EDGES + e]; ea = eattr[e]; }
    else { src = dst = e - E_EDGES; ea = g_ea_mean; }

    float p = 0.f;
    if (lane < 8) {
        const float4* xl4 = (const float4*)g_xl1;
        const float4* xr4 = (const float4*)g_xr1;
        const float4* We4 = (const float4*)We;
        const float4* at4 = (const float4*)att;
        float4 a = xl4[src * 8 + lane], b = xr4[dst * 8 + lane];
        float4 w = We4[lane], t = at4[lane];
        p = lrelu(a.x + b.x + ea * w.x) * t.x
          + lrelu(a.y + b.y + ea * w.y) * t.y
          + lrelu(a.z + b.z + ea * w.z) * t.z
          + lrelu(a.w + b.w + ea * w.w) * t.w;
    }
    p += __shfl_xor_sync(0xffffffffu, p, 1);
    p += __shfl_xor_sync(0xffffffffu, p, 2);
    if (lane == 0) {
        g_logit1[e * 2 + 0] = p;
        atomicMaxF(&g_max1[dst * 2 + 0], p);
    }
    if (lane == 4) {
        g_logit1[e * 2 + 1] = p;
        atomicMaxF(&g_max1[dst * 2 + 1], p);
    }
}

// ---------------- layer-1 aggregation ----------------
__global__ void k_agg1(const int* __restrict__ ei) {
    int e = blockIdx.x * (blockDim.x >> 5) + (threadIdx.x >> 5);
    if (e >= E_TOT) return;
    int lane = threadIdx.x & 31;
    int src, dst;
    if (e < E_EDGES) { src = ei[e]; dst = ei[E_EDGES + e]; }
    else { src = dst = e - E_EDGES; }
    if (lane < 8) {
        int h = lane >> 2;
        float al = g_ex1[e * 2 + h] / (g_sum1[dst * 2 + h] + 1e-16f);
        const float4* xl4 = (const float4*)g_xl1;
        float4 v = xl4[src * 8 + lane];
        float* o = &g_out1[dst * DOUT + lane * 4];
        atomicAdd(o + 0, al * v.x);
        atomicAdd(o + 1, al * v.y);
        atomicAdd(o + 2, al * v.z);
        atomicAdd(o + 3, al * v.w);
    }
}

// ---------------- final bias + LN + ReLU (DOUT=32): warp per node ----------------
__global__ void k_final_ln(const float* __restrict__ bias1, const float* __restrict__ g1,
                           const float* __restrict__ be1, float* __restrict__ out) {
    int r = blockIdx.x * (blockDim.x >> 5) + (threadIdx.x >> 5);
    if (r >= N_NODES) return;
    int lane = threadIdx.x & 31;
    float t = g_out1[r * DOUT + lane] + bias1[lane];
    float s = warp_sum(t);
    float sq = warp_sum(t * t);
    float mu = s / 32.f;
    float var = sq / 32.f - mu * mu;
    float rs = rsqrtf(var + 1e-5f);
    float o = (t - mu) * rs * g1[lane] + be1[lane];
    out[r * DOUT + lane] = fmaxf(0.f, o);
}

// ---------------- launch ----------------
extern "C" void kernel_launch(void* const* d_in, const int* in_sizes, int n_in,
                              void* d_out, int out_size) {
    const float* x     = (const float*)d_in[0];
    const int*   ei    = (const int*)d_in[1];
    const float* eattr = (const float*)d_in[2];
    const float* Wp    = (const float*)d_in[3];
    const float* bp    = (const float*)d_in[4];
    const float* Wl0   = (const float*)d_in[5];
    const float* bl0   = (const float*)d_in[6];
    const float* Wr0   = (const float*)d_in[7];
    const float* br0   = (const float*)d_in[8];
    const float* We0   = (const float*)d_in[9];
    const float* att0  = (const float*)d_in[10];
    const float* bias0 = (const float*)d_in[11];
    const float* g0    = (const float*)d_in[12];
    const float* be0   = (const float*)d_in[13];
    const float* Wl1   = (const float*)d_in[14];
    const float* bl1   = (const float*)d_in[15];
    const float* Wr1   = (const float*)d_in[16];
    const float* br1   = (const float*)d_in[17];
    const float* We1   = (const float*)d_in[18];
    const float* att1  = (const float*)d_in[19];
    const float* bias1 = (const float*)d_in[20];
    const float* g1    = (const float*)d_in[21];
    const float* be1   = (const float*)d_in[22];
    float* out = (float*)d_out;

    float *hidden, *xl0, *xr0, *xl1, *xr1;
    cudaGetSymbolAddress((void**)&hidden, g_hidden);
    cudaGetSymbolAddress((void**)&xl0, g_xl0);
    cudaGetSymbolAddress((void**)&xr0, g_xr0);
    cudaGetSymbolAddress((void**)&xl1, g_xl1);
    cudaGetSymbolAddress((void**)&xr1, g_xr1);
    float *h1;
    cudaGetSymbolAddress((void**)&h1, g_h1);
    float *logit0, *ex0, *logit1, *ex1, *max0, *sum0, *max1, *sum1;
    cudaGetSymbolAddress((void**)&logit0, g_logit0);
    cudaGetSymbolAddress((void**)&ex0, g_ex0);
    cudaGetSymbolAddress((void**)&logit1, g_logit1);
    cudaGetSymbolAddress((void**)&ex1, g_ex1);
    cudaGetSymbolAddress((void**)&max0, g_max0);
    cudaGetSymbolAddress((void**)&sum0, g_sum0);
    cudaGetSymbolAddress((void**)&max1, g_max1);
    cudaGetSymbolAddress((void**)&sum1, g_sum1);

    k_init<<<2048, 256>>>();
    k_eamean<<<1, 1024>>>(eattr);

    // hidden = x @ Wp + bp      [10000,512]x[512,256]
    {
        dim3 grid(256 / 64, (N_NODES + 63) / 64);
        sgemm_bias<64, 64, 16, 4, 4><<<grid, 256>>>(x, Wp, bp, hidden, N_NODES, 256, 512);
    }
    // xl0 / xr0 = hidden @ Wl0/Wr0 + b
    {
        dim3 grid(256 / 64, (N_NODES + 63) / 64);
        sgemm_bias<64, 64, 16, 4, 4><<<grid, 256>>>(hidden, Wl0, bl0, xl0, N_NODES, 256, 256);
        sgemm_bias<64, 64, 16, 4, 4><<<grid, 256>>>(hidden, Wr0, br0, xr0, N_NODES, 256, 256);
    }

    const int EWBLK = (E_TOT + 7) / 8;  // warp per edge, 8 warps/block
    k_logits0<<<EWBLK, 256>>>(ei, eattr, att0, We0);
    k_expsum<<<(E_TOT * 2 + 255) / 256, 256>>>(ei, logit0, max0, ex0, sum0);
    k_agg0<<<EWBLK, 256>>>(ei);
    k_resid_ln0<<<(N_NODES + 7) / 8, 256>>>(bias0, g0, be0);

    // layer-1 linear transforms: [10000,256]x[256,32]
    {
        dim3 grid(1, (N_NODES + 63) / 64);
        sgemm_bias<64, 32, 16, 4, 2><<<grid, 256>>>(h1, Wl1, bl1, xl1, N_NODES, 32, 256);
        sgemm_bias<64, 32, 16, 4, 2><<<grid, 256>>>(h1, Wr1, br1, xr1, N_NODES, 32, 256);
    }

    k_logits1<<<EWBLK, 256>>>(ei, eattr, att1, We1);
    k_expsum<<<(E_TOT * 2 + 255) / 256, 256>>>(ei, logit1, max1, ex1, sum1);
    k_agg1<<<EWBLK, 256>>>(ei);
    k_final_ln<<<(N_NODES + 7) / 8, 256>>>(bias1, g1, be1, out);
}

// round 3
// speedup vs baseline: 2.0136x; 2.0136x over previous
#include <cuda_runtime.h>
#include <math.h>

#define N_NODES 10000
#define E_EDGES 320000
#define E_TOT   330000   // + self loops
#define HID     256
#define DOUT    32

// ---------------- scratch (device globals) ----------------
__device__ float g_hidden[N_NODES * HID];
__device__ float g_xl0[N_NODES * HID];
__device__ float g_xr0[N_NODES * HID];
__device__ float g_h1[N_NODES * HID];
__device__ float g_xl1[N_NODES * DOUT];
__device__ float g_xr1[N_NODES * DOUT];
__device__ int   g_count[N_NODES];
__device__ int   g_off[N_NODES + 1];
__device__ int   g_cursor[N_NODES];
__device__ int   g_ssrc[E_TOT];
__device__ float g_sea[E_TOT];
__device__ float g_ea_mean;

// ---------------- helpers ----------------
__device__ __forceinline__ float lrelu(float v) { return v > 0.f ? v : 0.2f * v; }

__device__ __forceinline__ float warp_sum(float v) {
    #pragma unroll
    for (int o = 16; o > 0; o >>= 1) v += __shfl_xor_sync(0xffffffffu, v, o);
    return v;
}

// ---------------- init: counts = 1 (self loop pre-counted) ----------------
__global__ void k_init() {
    int i = blockIdx.x * blockDim.x + threadIdx.x;
    if (i < N_NODES) g_count[i] = 1;
}

// ---------------- edge_attr mean (ED=1) ----------------
__global__ void k_eamean(const float* __restrict__ ea) {
    __shared__ float sh[1024];
    float s = 0.f;
    for (int i = threadIdx.x; i < E_EDGES; i += 1024) s += ea[i];
    sh[threadIdx.x] = s;
    __syncthreads();
    for (int o = 512; o > 0; o >>= 1) {
        if (threadIdx.x < o) sh[threadIdx.x] += sh[threadIdx.x + o];
        __syncthreads();
    }
    if (threadIdx.x == 0) g_ea_mean = sh[0] / (float)E_EDGES;
}

// ---------------- histogram by dst ----------------
__global__ void k_hist(const int* __restrict__ ei) {
    int e = blockIdx.x * blockDim.x + threadIdx.x;
    if (e < E_EDGES) atomicAdd(&g_count[ei[E_EDGES + e]], 1);
}

// ---------------- 1-block exclusive scan (10001 offsets) + self-loop placement ----------------
__global__ void k_scan() {
    __shared__ int sh[1024];
    const int t = threadIdx.x;
    const int CH = 10;                 // 1024*10 >= 10001
    int base = t * CH;
    int local[CH];
    int s = 0;
    #pragma unroll
    for (int i = 0; i < CH; i++) {
        int idx = base + i;
        int v = (idx < N_NODES) ? g_count[idx] : 0;
        local[i] = s;
        s += v;
    }
    sh[t] = s;
    __syncthreads();
    for (int o = 1; o < 1024; o <<= 1) {
        int v = (t >= o) ? sh[t - o] : 0;
        __syncthreads();
        sh[t] += v;
        __syncthreads();
    }
    int pre = (t > 0) ? sh[t - 1] : 0;
    float eam = g_ea_mean;
    #pragma unroll
    for (int i = 0; i < CH; i++) {
        int idx = base + i;
        if (idx <= N_NODES) {
            int off = pre + local[i];
            g_off[idx] = off;
            if (idx < N_NODES) {
                // deterministic self-loop in first slot
                g_ssrc[off] = idx;
                g_sea[off] = eam;
                g_cursor[idx] = off + 1;
            }
        }
    }
}

// ---------------- scatter real edges into CSR-by-dst ----------------
__global__ void k_scatter(const int* __restrict__ ei, const float* __restrict__ eattr) {
    int e = blockIdx.x * blockDim.x + threadIdx.x;
    if (e >= E_EDGES) return;
    int src = ei[e], dst = ei[E_EDGES + e];
    int pos = atomicAdd(&g_cursor[dst], 1);
    g_ssrc[pos] = src;
    g_sea[pos] = eattr[e];
}

// ---------------- tiled SGEMM with bias: C = A[M,K] @ B[K,Nc] + bias ----------------
template<int BM, int BN, int BK, int TM, int TN>
__global__ void sgemm2(const float* __restrict__ A, const float* __restrict__ B,
                       const float* __restrict__ bias, float* __restrict__ C,
                       int M, int Nc, int K) {
    __shared__ float As[BK][BM + 4];
    __shared__ float Bs[BK][BN + 4];
    constexpr int TX = BN / TN;
    constexpr int TY = BM / TM;
    constexpr int NT = TX * TY;
    const int tid = threadIdx.x;
    const int tx = tid % TX, ty = tid / TX;
    const int row0 = blockIdx.y * BM, col0 = blockIdx.x * BN;

    float acc[TM][TN];
    #pragma unroll
    for (int m = 0; m < TM; m++)
        #pragma unroll
        for (int n = 0; n < TN; n++) acc[m][n] = 0.f;

    for (int k0 = 0; k0 < K; k0 += BK) {
        // A tile: float4 loads, transpose-store
        for (int i = tid; i < BM * BK / 4; i += NT) {
            int lin = i * 4;
            int r = lin / BK, c = lin % BK;
            int gr = row0 + r;
            float4 v = (gr < M) ? *(const float4*)&A[(size_t)gr * K + k0 + c]
                                : make_float4(0.f, 0.f, 0.f, 0.f);
            As[c + 0][r] = v.x; As[c + 1][r] = v.y;
            As[c + 2][r] = v.z; As[c + 3][r] = v.w;
        }
        // B tile: float4 load + float4 store
        for (int i = tid; i < BK * BN / 4; i += NT) {
            int lin = i * 4;
            int kr = lin / BN, c = lin % BN;
            *(float4*)&Bs[kr][c] = *(const float4*)&B[(size_t)(k0 + kr) * Nc + col0 + c];
        }
        __syncthreads();
        #pragma unroll
        for (int kk = 0; kk < BK; kk++) {
            float a[TM], b[TN];
            #pragma unroll
            for (int m = 0; m < TM; m++) a[m] = As[kk][ty * TM + m];
            #pragma unroll
            for (int n = 0; n < TN; n++) b[n] = Bs[kk][tx * TN + n];
            #pragma unroll
            for (int m = 0; m < TM; m++)
                #pragma unroll
                for (int n = 0; n < TN; n++) acc[m][n] += a[m] * b[n];
        }
        __syncthreads();
    }
    #pragma unroll
    for (int m = 0; m < TM; m++) {
        int gr = row0 + ty * TM + m;
        if (gr >= M) continue;
        #pragma unroll
        for (int n = 0; n < TN; n++) {
            int gc = col0 + tx * TN + n;
            C[(size_t)gr * Nc + gc] = acc[m][n] + bias[gc];
        }
    }
}

// ---------------- fused layer-0: online-softmax GAT + bias + residual + LN + ReLU ----------------
// warp per dst node; next-edge index prefetch to hide the ssrc->gather chain
__global__ void k_node0(const float* __restrict__ We, const float* __restrict__ att,
                        const float* __restrict__ bias0, const float* __restrict__ g0,
                        const float* __restrict__ be0) {
    int r = blockIdx.x * (blockDim.x >> 5) + (threadIdx.x >> 5);
    if (r >= N_NODES) return;
    int lane = threadIdx.x & 31;

    const float4* xl4 = (const float4*)g_xl0;
    const float4* xr4 = (const float4*)g_xr0;
    const float4* We4 = (const float4*)We;
    const float4* at4 = (const float4*)att;

    float4 xra = xr4[r * 64 + lane],      xrb = xr4[r * 64 + lane + 32];
    float4 wea = We4[lane],               web = We4[lane + 32];
    float4 ata = at4[lane],               atb = at4[lane + 32];

    const float NINF = __int_as_float(0xFF800000);
    float m0 = NINF, s0 = 0.f, m1 = NINF, s1 = 0.f;
    float4 acc0 = make_float4(0.f, 0.f, 0.f, 0.f);
    float4 acc1 = make_float4(0.f, 0.f, 0.f, 0.f);

    int beg = g_off[r], end = g_off[r + 1];
    int src = g_ssrc[beg];
    float ea = g_sea[beg];
    for (int j = beg; j < end; j++) {
        // prefetch next edge scalars (overlaps with this iteration's math)
        int nsrc = 0; float nea = 0.f;
        if (j + 1 < end) { nsrc = g_ssrc[j + 1]; nea = g_sea[j + 1]; }

        float4 a = xl4[src * 64 + lane];
        float4 b = xl4[src * 64 + lane + 32];

        float p0 = lrelu(a.x + xra.x + ea * wea.x) * ata.x
                 + lrelu(a.y + xra.y + ea * wea.y) * ata.y
                 + lrelu(a.z + xra.z + ea * wea.z) * ata.z
                 + lrelu(a.w + xra.w + ea * wea.w) * ata.w;
        float p1 = lrelu(b.x + xrb.x + ea * web.x) * atb.x
                 + lrelu(b.y + xrb.y + ea * web.y) * atb.y
                 + lrelu(b.z + xrb.z + ea * web.z) * atb.z
                 + lrelu(b.w + xrb.w + ea * web.w) * atb.w;
        #pragma unroll
        for (int o = 16; o > 0; o >>= 1) {
            p0 += __shfl_xor_sync(0xffffffffu, p0, o);
            p1 += __shfl_xor_sync(0xffffffffu, p1, o);
        }
        // online softmax, head 0
        if (p0 > m0) {
            float c = __expf(m0 - p0);
            s0 *= c;
            acc0.x *= c; acc0.y *= c; acc0.z *= c; acc0.w *= c;
            m0 = p0;
        }
        float w0 = __expf(p0 - m0);
        s0 += w0;
        acc0.x += w0 * a.x; acc0.y += w0 * a.y;
        acc0.z += w0 * a.z; acc0.w += w0 * a.w;
        // head 1
        if (p1 > m1) {
            float c = __expf(m1 - p1);
            s1 *= c;
            acc1.x *= c; acc1.y *= c; acc1.z *= c; acc1.w *= c;
            m1 = p1;
        }
        float w1 = __expf(p1 - m1);
        s1 += w1;
        acc1.x += w1 * b.x; acc1.y += w1 * b.y;
        acc1.z += w1 * b.z; acc1.w += w1 * b.w;

        src = nsrc; ea = nea;
    }

    float inv0 = 1.f / (s0 + 1e-16f);
    float inv1 = 1.f / (s1 + 1e-16f);

    const float4* b4 = (const float4*)bias0;
    const float4* h4 = (const float4*)g_hidden;
    float4 bia = b4[lane], bib = b4[lane + 32];
    float4 ha = h4[r * 64 + lane], hb = h4[r * 64 + lane + 32];

    float4 v0, v1;
    v0.x = acc0.x * inv0 + bia.x + ha.x; v0.y = acc0.y * inv0 + bia.y + ha.y;
    v0.z = acc0.z * inv0 + bia.z + ha.z; v0.w = acc0.w * inv0 + bia.w + ha.w;
    v1.x = acc1.x * inv1 + bib.x + hb.x; v1.y = acc1.y * inv1 + bib.y + hb.y;
    v1.z = acc1.z * inv1 + bib.z + hb.z; v1.w = acc1.w * inv1 + bib.w + hb.w;

    float s  = v0.x + v0.y + v0.z + v0.w + v1.x + v1.y + v1.z + v1.w;
    float sq = v0.x * v0.x + v0.y * v0.y + v0.z * v0.z + v0.w * v0.w
             + v1.x * v1.x + v1.y * v1.y + v1.z * v1.z + v1.w * v1.w;
    s = warp_sum(s);
    sq = warp_sum(sq);
    float mu = s / 256.f;
    float var = sq / 256.f - mu * mu;
    float rs = rsqrtf(var + 1e-5f);

    const float4* gg4 = (const float4*)g0;
    const float4* bb4 = (const float4*)be0;
    float4 ga = gg4[lane], gb = gg4[lane + 32];
    float4 ba = bb4[lane], bb = bb4[lane + 32];
    float4* out4 = (float4*)g_h1;
    float4 o0, o1;
    o0.x = fmaxf(0.f, (v0.x - mu) * rs * ga.x + ba.x);
    o0.y = fmaxf(0.f, (v0.y - mu) * rs * ga.y + ba.y);
    o0.z = fmaxf(0.f, (v0.z - mu) * rs * ga.z + ba.z);
    o0.w = fmaxf(0.f, (v0.w - mu) * rs * ga.w + ba.w);
    o1.x = fmaxf(0.f, (v1.x - mu) * rs * gb.x + bb.x);
    o1.y = fmaxf(0.f, (v1.y - mu) * rs * gb.y + bb.y);
    o1.z = fmaxf(0.f, (v1.z - mu) * rs * gb.z + bb.z);
    o1.w = fmaxf(0.f, (v1.w - mu) * rs * gb.w + bb.w);
    out4[r * 64 + lane] = o0;
    out4[r * 64 + lane + 32] = o1;
}

// ---------------- fused layer-1: online-softmax GAT + bias + LN + ReLU ----------------
// warp per dst node, lane = dim (32 dims, head = lane/16)
__global__ void k_node1(const float* __restrict__ We, const float* __restrict__ att,
                        const float* __restrict__ bias1, const float* __restrict__ g1,
                        const float* __restrict__ be1, float* __restrict__ out) {
    int r = blockIdx.x * (blockDim.x >> 5) + (threadIdx.x >> 5);
    if (r >= N_NODES) return;
    int lane = threadIdx.x & 31;

    float xr = g_xr1[r * DOUT + lane];
    float we = We[lane];
    float at = att[lane];

    const float NINF = __int_as_float(0xFF800000);
    float m = NINF, s = 0.f, acc = 0.f;

    int beg = g_off[r], end = g_off[r + 1];
    int src = g_ssrc[beg];
    float ea = g_sea[beg];
    for (int j = beg; j < end; j++) {
        int nsrc = 0; float nea = 0.f;
        if (j + 1 < end) { nsrc = g_ssrc[j + 1]; nea = g_sea[j + 1]; }

        float xj = g_xl1[src * DOUT + lane];
        float p = lrelu(xj + xr + ea * we) * at;
        // reduce within 16-lane half (per-head logit)
        #pragma unroll
        for (int o = 8; o > 0; o >>= 1) p += __shfl_xor_sync(0xffffffffu, p, o);
        if (p > m) {
            float c = __expf(m - p);
            s *= c;
            acc *= c;
            m = p;
        }
        float w = __expf(p - m);
        s += w;
        acc += w * xj;

        src = nsrc; ea = nea;
    }

    float t = acc / (s + 1e-16f) + bias1[lane];
    float su = warp_sum(t);
    float sq = warp_sum(t * t);
    float mu = su / 32.f;
    float var = sq / 32.f - mu * mu;
    float rs = rsqrtf(var + 1e-5f);
    out[r * DOUT + lane] = fmaxf(0.f, (t - mu) * rs * g1[lane] + be1[lane]);
}

// ---------------- launch ----------------
extern "C" void kernel_launch(void* const* d_in, const int* in_sizes, int n_in,
                              void* d_out, int out_size) {
    const float* x     = (const float*)d_in[0];
    const int*   ei    = (const int*)d_in[1];
    const float* eattr = (const float*)d_in[2];
    const float* Wp    = (const float*)d_in[3];
    const float* bp    = (const float*)d_in[4];
    const float* Wl0   = (const float*)d_in[5];
    const float* bl0   = (const float*)d_in[6];
    const float* Wr0   = (const float*)d_in[7];
    const float* br0   = (const float*)d_in[8];
    const float* We0   = (const float*)d_in[9];
    const float* att0  = (const float*)d_in[10];
    const float* bias0 = (const float*)d_in[11];
    const float* g0    = (const float*)d_in[12];
    const float* be0   = (const float*)d_in[13];
    const float* Wl1   = (const float*)d_in[14];
    const float* bl1   = (const float*)d_in[15];
    const float* Wr1   = (const float*)d_in[16];
    const float* br1   = (const float*)d_in[17];
    const float* We1   = (const float*)d_in[18];
    const float* att1  = (const float*)d_in[19];
    const float* bias1 = (const float*)d_in[20];
    const float* g1    = (const float*)d_in[21];
    const float* be1   = (const float*)d_in[22];
    float* out = (float*)d_out;

    float *hidden, *xl0, *xr0, *h1, *xl1, *xr1;
    cudaGetSymbolAddress((void**)&hidden, g_hidden);
    cudaGetSymbolAddress((void**)&xl0, g_xl0);
    cudaGetSymbolAddress((void**)&xr0, g_xr0);
    cudaGetSymbolAddress((void**)&h1, g_h1);
    cudaGetSymbolAddress((void**)&xl1, g_xl1);
    cudaGetSymbolAddress((void**)&xr1, g_xr1);

    // CSR build
    k_init<<<(N_NODES + 255) / 256, 256>>>();
    k_eamean<<<1, 1024>>>(eattr);
    k_hist<<<(E_EDGES + 255) / 256, 256>>>(ei);
    k_scan<<<1, 1024>>>();
    k_scatter<<<(E_EDGES + 255) / 256, 256>>>(ei, eattr);

    // hidden = x @ Wp + bp   [10000,512]x[512,256]
    {
        dim3 grid(256 / 64, (N_NODES + 127) / 128);
        sgemm2<128, 64, 16, 8, 4><<<grid, 256>>>(x, Wp, bp, hidden, N_NODES, 256, 512);
    }
    // xl0 / xr0
    {
        dim3 grid(256 / 64, (N_NODES + 127) / 128);
        sgemm2<128, 64, 16, 8, 4><<<grid, 256>>>(hidden, Wl0, bl0, xl0, N_NODES, 256, 256);
        sgemm2<128, 64, 16, 8, 4><<<grid, 256>>>(hidden, Wr0, br0, xr0, N_NODES, 256, 256);
    }

    // fused layer-0 (logits + softmax + agg + bias + residual + LN + ReLU)
    k_node0<<<(N_NODES + 7) / 8, 256>>>(We0, att0, bias0, g0, be0);

    // layer-1 linear transforms [10000,256]x[256,32]
    {
        dim3 grid(1, (N_NODES + 127) / 128);
        sgemm2<128, 32, 16, 8, 2><<<grid, 256>>>(h1, Wl1, bl1, xl1, N_NODES, 32, 256);
        sgemm2<128, 32, 16, 8, 2><<<grid, 256>>>(h1, Wr1, br1, xr1, N_NODES, 32, 256);
    }

    // fused layer-1
    k_node1<<<(N_NODES + 7) / 8, 256>>>(We1, att1, bias1, g1, be1, out);
}